// round 10
// baseline (speedup 1.0000x reference)
#include <cuda_runtime.h>
#include <cuda_fp16.h>
#include <cstdint>

// ============================================================================
// DigitConvolutionalModel: out = relu(conv3x3(x) @ w1 + b1) @ w2 + b2
// Folded:  out = relu(x @ W1eff + b1) @ w2 + b2,   W1eff = C @ w1   [784,128]
//
// R8: single-barrier pipeline. A16(c+1) is STS'd into the other stage during
// iteration c, so each iteration is: wait_group 0; sync; {issue B(c+1),
// STS A16(c+1), LDG A(c+2), MMA(c)} in one barrier-free block. 2 CTAs/SM.
// ============================================================================

#define B_ROWS   65536
#define K_REAL   784
#define NPAIR    7           // 7 * 128 = 896 >= 784 (zero padded)
#define NCH64    14          // 64-wide B chunks incl. zero pad
#define BM       64
#define BN       128
#define THREADS  256

// ---- dynamic smem layout ----
#define A16_OFF     0          // 2 subs x (64x64 fp16 = 8192) = 16384
#define B_OFF       16384      // 2 subs x (128x64 fp16 = 16384) = 32768
#define STAGE_BYTES 49152
#define SM_B1       98304      // 128 fp32
#define SM_W2       98816      // 1280 fp32
#define SM_PACC     103936     // 640 fp32
#define SMEM_TOTAL  106496     // 104 KB -> 2 CTAs/SM

// Pre-swizzled W1eff^T tiles: [chunk64][128n x 64k] fp16 (chunks 12,13 zero-padded).
__device__ __align__(16) __half g_B[NCH64][128 * 64];

// -------------------- helpers --------------------
__device__ __forceinline__ uint32_t smem_u32(const void* p) {
    uint32_t a;
    asm("{ .reg .u64 t; cvta.to.shared.u64 t, %1; cvt.u32.u64 %0, t; }" : "=r"(a) : "l"(p));
    return a;
}
__device__ __forceinline__ uint32_t sw128(uint32_t off) {
    return off ^ ((off >> 3) & 0x70);
}
__device__ __forceinline__ void cp_async16(uint32_t dst, const void* src) {
    asm volatile("cp.async.cg.shared.global [%0], [%1], 16;" :: "r"(dst), "l"(src) : "memory");
}
__device__ __forceinline__ void cp_commit() {
    asm volatile("cp.async.commit_group;" ::: "memory");
}
__device__ __forceinline__ void ldmatrix_x4(uint32_t& d0, uint32_t& d1, uint32_t& d2,
                                            uint32_t& d3, uint32_t addr) {
    asm volatile("ldmatrix.sync.aligned.m8n8.x4.shared.b16 {%0,%1,%2,%3}, [%4];"
                 : "=r"(d0), "=r"(d1), "=r"(d2), "=r"(d3) : "r"(addr));
}
__device__ __forceinline__ void mma16816(float* d, const uint32_t* a, const uint32_t* b) {
    asm volatile(
        "mma.sync.aligned.m16n8k16.row.col.f32.f16.f16.f32 "
        "{%0,%1,%2,%3}, {%4,%5,%6,%7}, {%8,%9}, {%0,%1,%2,%3};"
        : "+f"(d[0]), "+f"(d[1]), "+f"(d[2]), "+f"(d[3])
        : "r"(a[0]), "r"(a[1]), "r"(a[2]), "r"(a[3]), "r"(b[0]), "r"(b[1]));
}

// ============================================================================
// Prep: W1eff^T = (C @ w1)^T -> fp16, per-64-chunk SW128-swizzled [n][k].
// ============================================================================
__global__ void prep_kernel(const float* __restrict__ conv_w, const float* __restrict__ w1) {
    int idx = blockIdx.x * blockDim.x + threadIdx.x;
    if (idx >= NCH64 * 128 * 64) return;
    int chunk = idx >> 13;
    int rem = idx & 8191;
    int n = rem >> 6;
    int kk = rem & 63;
    int k = chunk * 64 + kk;
    float v = 0.f;
    if (k < K_REAL) {
        int r = k / 28, c = k % 28;
        #pragma unroll
        for (int di = 0; di < 3; di++) {
            int oi = r - di;
            if (oi < 0 || oi > 25) continue;
            #pragma unroll
            for (int dj = 0; dj < 3; dj++) {
                int oj = c - dj;
                if (oj < 0 || oj > 25) continue;
                v += conv_w[di * 3 + dj] * w1[(oi * 26 + oj) * 128 + n];
            }
        }
    }
    uint32_t sw = sw128((uint32_t)(n * 128 + kk * 2));
    g_B[chunk][sw >> 1] = __float2half_rn(v);
}

// ============================================================================
// Main kernel. 8 warps: mg = wid&1 (m32), ng = wid>>1 (n32).
// ============================================================================
__global__ __launch_bounds__(THREADS, 2)
void digitconv_main(const float* __restrict__ x, const float* __restrict__ b1,
                    const float* __restrict__ w2, const float* __restrict__ b2,
                    float* __restrict__ out) {
    extern __shared__ char smem[];
    const uint32_t sbase = smem_u32(smem);
    const int tid = threadIdx.x;
    const int wid = tid >> 5;
    const int lane = tid & 31;
    const int wm = (wid & 1) * 32;       // 2 m-groups of 32
    const int wn = (wid >> 1) * 32;      // 4 n-groups of 32
    const size_t m0 = (size_t)blockIdx.x * BM;

    float* b1s  = (float*)(smem + SM_B1);
    float* w2s  = (float*)(smem + SM_W2);
    float* pacc = (float*)(smem + SM_PACC);

    if (tid < 128) b1s[tid] = b1[tid];
    for (int i = tid; i < 1280; i += THREADS) w2s[i] = w2[i];
    for (int i = tid; i < BM * 10; i += THREADS) pacc[i] = 0.f;

    float acc[2][4][4];
    #pragma unroll
    for (int tm = 0; tm < 2; tm++)
        #pragma unroll
        for (int tn = 0; tn < 4; tn++)
            #pragma unroll
            for (int e = 0; e < 4; e++) acc[tm][tn][e] = 0.f;

    // per-thread A addressing: i = q*256+tid, sub=i>>10, row=(i&1023)>>4, c4=i&15
    const int i_lo = tid;
    float4 areg[8];

    auto ldg_pair = [&](int p) {
        #pragma unroll
        for (int q = 0; q < 8; q++) {
            int i = q * THREADS + i_lo;
            int sub = i >> 10;
            int rem = i & 1023;
            int row = rem >> 4;
            int c4 = rem & 15;
            int gcol = p * 128 + sub * 64 + c4 * 4;
            if (gcol < K_REAL)
                areg[q] = *reinterpret_cast<const float4*>(x + (m0 + row) * K_REAL + gcol);
            else
                areg[q] = make_float4(0.f, 0.f, 0.f, 0.f);
        }
    };
    auto sts_pair = [&](uint32_t st) {
        #pragma unroll
        for (int q = 0; q < 8; q++) {
            int i = q * THREADS + i_lo;
            int sub = i >> 10;
            int rem = i & 1023;
            int row = rem >> 4;
            int c4 = rem & 15;
            __half2 h0 = __floats2half2_rn(areg[q].x, areg[q].y);
            __half2 h1 = __floats2half2_rn(areg[q].z, areg[q].w);
            uint2 w;
            w.x = *reinterpret_cast<uint32_t*>(&h0);
            w.y = *reinterpret_cast<uint32_t*>(&h1);
            uint32_t dst = st + A16_OFF + sub * 8192 + sw128((uint32_t)(row * 128 + c4 * 8));
            asm volatile("st.shared.v2.b32 [%0], {%1, %2};" :: "r"(dst), "r"(w.x), "r"(w.y)
                         : "memory");
        }
    };
    auto issue_b = [&](int p, uint32_t st) {
        const char* gb = (const char*)&g_B[2 * p][0];   // 32KB contiguous (2 chunks)
        #pragma unroll
        for (int q = 0; q < 8; q++) {
            int i = q * THREADS + i_lo;
            cp_async16(st + B_OFF + i * 16, gb + i * 16);
        }
        cp_commit();
    };

    // prologue: A16(0)+B(0) into stage 0, A(1) into registers
    ldg_pair(0);
    issue_b(0, sbase);
    sts_pair(sbase);
    ldg_pair(1);

    const int sel = lane >> 3;

    for (int c = 0; c < NPAIR; c++) {
        const uint32_t st  = sbase + (c & 1) * STAGE_BYTES;
        const uint32_t st2 = sbase + ((c & 1) ^ 1) * STAGE_BYTES;

        // B(c) complete (issued a full iteration ago), then make everything
        // (B(c) cp.asyncs, A16(c) STS from iter c-1) visible to all warps.
        asm volatile("cp.async.wait_group 0;" ::: "memory");
        __syncthreads();

        // One barrier-free block: next-iter loads + this-iter MMA interleave.
        if (c + 1 < NPAIR) {
            issue_b(c + 1, st2);        // B(c+1) -> other stage
            sts_pair(st2);              // A16(c+1) from areg -> other stage
            if (c + 2 < NPAIR) ldg_pair(c + 2);   // A(c+2) -> areg
        }

        #pragma unroll
        for (int sub = 0; sub < 2; sub++) {
            const uint32_t aB = st + A16_OFF + sub * 8192;
            const uint32_t bB = st + B_OFF + sub * 16384;
            #pragma unroll
            for (int ks = 0; ks < 4; ks++) {
                uint32_t afr[2][4];
                #pragma unroll
                for (int tm = 0; tm < 2; tm++) {
                    int r = wm + tm * 16 + (lane & 7) + ((sel & 1) << 3);
                    int kb = ks * 32 + ((sel >> 1) << 4);
                    ldmatrix_x4(afr[tm][0], afr[tm][1], afr[tm][2], afr[tm][3],
                                aB + sw128((uint32_t)(r * 128 + kb)));
                }
                uint32_t bf[4][2];
                #pragma unroll
                for (int tp = 0; tp < 2; tp++) {
                    int r = wn + (2 * tp + (sel >> 1)) * 8 + (lane & 7);
                    int kb = ks * 32 + ((sel & 1) << 4);
                    ldmatrix_x4(bf[2*tp][0], bf[2*tp][1], bf[2*tp+1][0], bf[2*tp+1][1],
                                bB + sw128((uint32_t)(r * 128 + kb)));
                }
                #pragma unroll
                for (int tm = 0; tm < 2; tm++)
                    #pragma unroll
                    for (int tn = 0; tn < 4; tn++)
                        mma16816(acc[tm][tn], afr[tm], bf[tn]);
            }
        }
    }

    // ---- Epilogue: relu(D + b1) @ w2, reduce, + b2, store ----
    #pragma unroll
    for (int tm = 0; tm < 2; tm++) {
        #pragma unroll
        for (int half = 0; half < 2; half++) {
            float p[10];
            #pragma unroll
            for (int j = 0; j < 10; j++) p[j] = 0.f;
            int r = wm + tm * 16 + (lane >> 2) + half * 8;
            #pragma unroll
            for (int tn = 0; tn < 4; tn++) {
                #pragma unroll
                for (int e = 0; e < 2; e++) {
                    int col = wn + tn * 8 + ((lane & 3) << 1) + e;
                    float v = acc[tm][tn][half * 2 + e] + b1s[col];
                    v = fmaxf(v, 0.f);
                    #pragma unroll
                    for (int j = 0; j < 10; j++) p[j] = fmaf(v, w2s[col * 10 + j], p[j]);
                }
            }
            #pragma unroll
            for (int j = 0; j < 10; j++) {
                p[j] += __shfl_xor_sync(0xFFFFFFFF, p[j], 1);
                p[j] += __shfl_xor_sync(0xFFFFFFFF, p[j], 2);
            }
            if ((lane & 3) == 0) {
                #pragma unroll
                for (int j = 0; j < 10; j++) atomicAdd(&pacc[r * 10 + j], p[j]);
            }
        }
    }
    __syncthreads();

    for (int i = tid; i < BM * 10; i += THREADS) {
        int r = i / 10, j = i - r * 10;
        out[(m0 + r) * 10 + j] = pacc[i] + __ldg(&b2[j]);
    }
}

// ============================================================================
extern "C" void kernel_launch(void* const* d_in, const int* in_sizes, int n_in,
                              void* d_out, int out_size) {
    const float* x      = (const float*)d_in[0];
    const float* conv_w = (const float*)d_in[1];
    const float* w1     = (const float*)d_in[2];
    const float* b1     = (const float*)d_in[3];
    const float* w2     = (const float*)d_in[4];
    const float* b2     = (const float*)d_in[5];
    float* out = (float*)d_out;

    cudaFuncSetAttribute(digitconv_main,
                         cudaFuncAttributeMaxDynamicSharedMemorySize, SMEM_TOTAL);

    prep_kernel<<<(NCH64 * 128 * 64 + 255) / 256, 256>>>(conv_w, w1);
    digitconv_main<<<B_ROWS / BM, THREADS, SMEM_TOTAL>>>(x, b1, w2, b2, out);
}